// round 5
// baseline (speedup 1.0000x reference)
#include <cuda_runtime.h>
#include <cuda_bf16.h>

#define B_ROWS 8192
#define ITEM_NUM 10000
#define THREADS 256
#define ROWS_PER_CTA 2
#define GRID (B_ROWS / ROWS_PER_CTA)

// Scratch (no cudaMalloc allowed).
__device__ float g_row_loss[B_ROWS];
__device__ unsigned int g_arrived = 0;   // reset by the last block each launch

__global__ __launch_bounds__(THREADS)
void dq_fused2_kernel(const float* __restrict__ hs,
                      const float* __restrict__ tq,
                      const float* __restrict__ rewards,
                      const float* __restrict__ discount,
                      const unsigned char* __restrict__ is_done,
                      const float* __restrict__ W,
                      const float* __restrict__ bias,
                      float* __restrict__ out) {
    const int row0 = blockIdx.x * ROWS_PER_CTA;
    const int row1 = row0 + 1;
    const float4* __restrict__ h0r = reinterpret_cast<const float4*>(hs + (size_t)row0 * ITEM_NUM);
    const float4* __restrict__ t0r = reinterpret_cast<const float4*>(tq + (size_t)row0 * ITEM_NUM);
    const float4* __restrict__ h1r = reinterpret_cast<const float4*>(hs + (size_t)row1 * ITEM_NUM);
    const float4* __restrict__ t1r = reinterpret_cast<const float4*>(tq + (size_t)row1 * ITEM_NUM);
    const float4* __restrict__ w4  = reinterpret_cast<const float4*>(W);
    const int n4 = ITEM_NUM / 4;  // 2500

    float q0 = 0.0f, n0 = 0.0f, q1 = 0.0f, n1 = 0.0f;
    for (int i = threadIdx.x; i < n4; i += THREADS) {
        float4 w  = w4[i];
        float4 h0 = h0r[i];
        float4 t0 = t0r[i];
        float4 h1 = h1r[i];
        float4 t1 = t1r[i];
        q0 = fmaf(h0.x, w.x, q0); q0 = fmaf(h0.y, w.y, q0);
        q0 = fmaf(h0.z, w.z, q0); q0 = fmaf(h0.w, w.w, q0);
        n0 = fmaf(t0.x, w.x, n0); n0 = fmaf(t0.y, w.y, n0);
        n0 = fmaf(t0.z, w.z, n0); n0 = fmaf(t0.w, w.w, n0);
        q1 = fmaf(h1.x, w.x, q1); q1 = fmaf(h1.y, w.y, q1);
        q1 = fmaf(h1.z, w.z, q1); q1 = fmaf(h1.w, w.w, q1);
        n1 = fmaf(t1.x, w.x, n1); n1 = fmaf(t1.y, w.y, n1);
        n1 = fmaf(t1.z, w.z, n1); n1 = fmaf(t1.w, w.w, n1);
    }

    // Warp reduce all four sums
    #pragma unroll
    for (int off = 16; off > 0; off >>= 1) {
        q0 += __shfl_down_sync(0xFFFFFFFFu, q0, off);
        n0 += __shfl_down_sync(0xFFFFFFFFu, n0, off);
        q1 += __shfl_down_sync(0xFFFFFFFFu, q1, off);
        n1 += __shfl_down_sync(0xFFFFFFFFu, n1, off);
    }

    __shared__ float4 sred[THREADS / 32];
    __shared__ bool   s_is_last;
    const int lane = threadIdx.x & 31;
    const int wid  = threadIdx.x >> 5;
    if (lane == 0) sred[wid] = make_float4(q0, n0, q1, n1);
    __syncthreads();

    if (threadIdx.x == 0) {
        float a = 0.0f, b_ = 0.0f, c = 0.0f, d = 0.0f;
        #pragma unroll
        for (int w = 0; w < THREADS / 32; w++) {
            float4 v = sred[w];
            a += v.x; b_ += v.y; c += v.z; d += v.w;
        }
        const float bb   = bias[0];
        const float disc = discount[0];
        const float qv0  = fmaxf(a + bb, 0.0f);
        const float nv0  = fmaxf(b_ + bb, 0.0f);
        const float qv1  = fmaxf(c + bb, 0.0f);
        const float nv1  = fmaxf(d + bb, 0.0f);
        float ps0 = fabsf(rewards[row0] + disc * nv0 - qv0);
        float ps1 = fabsf(rewards[row1] + disc * nv1 - qv1);
        if (is_done[row0]) ps0 = 0.0f;
        if (is_done[row1]) ps1 = 0.0f;
        // 8-byte aligned: row0 is even.
        *reinterpret_cast<float2*>(&g_row_loss[row0]) = make_float2(ps0, ps1);
        __threadfence();
        unsigned int prev = atomicAdd(&g_arrived, 1u);
        s_is_last = (prev == (unsigned int)(gridDim.x - 1));
    }
    __syncthreads();

    if (s_is_last) {
        __threadfence();
        __syncthreads();
        // Deterministic fixed-order reduction of all rows (vectorized).
        __shared__ float s[THREADS];
        const float4* rl4 = reinterpret_cast<const float4*>(g_row_loss);
        float sum = 0.0f;
        #pragma unroll
        for (int i = threadIdx.x; i < B_ROWS / 4; i += THREADS) {
            float4 v = rl4[i];
            sum += (v.x + v.y) + (v.z + v.w);
        }
        s[threadIdx.x] = sum;
        __syncthreads();
        #pragma unroll
        for (int st = THREADS / 2; st > 0; st >>= 1) {
            if (threadIdx.x < st) s[threadIdx.x] += s[threadIdx.x + st];
            __syncthreads();
        }
        if (threadIdx.x == 0) {
            out[0] = s[0] / (float)B_ROWS;
            g_arrived = 0;  // reset for next graph replay
        }
    }
}

extern "C" void kernel_launch(void* const* d_in, const int* in_sizes, int n_in,
                              void* d_out, int out_size) {
    const float*         hs       = (const float*)d_in[0];
    // d_in[1] = actions (unused by reference)
    const float*         rewards  = (const float*)d_in[2];
    const float*         discount = (const float*)d_in[3];
    const float*         tq       = (const float*)d_in[4];
    const unsigned char* is_done  = (const unsigned char*)d_in[5];
    const float*         W        = (const float*)d_in[6];
    const float*         bias     = (const float*)d_in[7];
    float* out = (float*)d_out;

    dq_fused2_kernel<<<GRID, THREADS>>>(hs, tq, rewards, discount, is_done, W, bias, out);
}

// round 6
// speedup vs baseline: 1.0332x; 1.0332x over previous
#include <cuda_runtime.h>
#include <cuda_bf16.h>

#define B_ROWS 8192
#define ITEM_NUM 10000
#define THREADS 256
#define N4 (ITEM_NUM / 4)            /* 2500 float4 per row */
#define FULL_ITERS (N4 / THREADS)    /* 9 */
#define REMAIN (N4 - FULL_ITERS * THREADS) /* 196 */

// Scratch (no cudaMalloc allowed).
__device__ float g_row_loss[B_ROWS];
__device__ unsigned int g_arrived = 0;   // reset by the last block each launch

__global__ __launch_bounds__(THREADS)
void dq_fused_kernel(const float* __restrict__ hs,
                     const float* __restrict__ tq,
                     const float* __restrict__ rewards,
                     const float* __restrict__ discount,
                     const unsigned char* __restrict__ is_done,
                     const float* __restrict__ W,
                     const float* __restrict__ bias,
                     float* __restrict__ out) {
    const int row = blockIdx.x;
    const float4* __restrict__ hsr = reinterpret_cast<const float4*>(hs + (size_t)row * ITEM_NUM);
    const float4* __restrict__ tqr = reinterpret_cast<const float4*>(tq + (size_t)row * ITEM_NUM);
    const float4* __restrict__ w4  = reinterpret_cast<const float4*>(W);

    float qs = 0.0f, ns = 0.0f;

    // Main body: compile-time trip count -> unrollable, batches LDG.128s.
    #pragma unroll 3
    for (int k = 0; k < FULL_ITERS; k++) {
        const int i = threadIdx.x + k * THREADS;
        float4 w = w4[i];
        float4 h = __ldcs(&hsr[i]);   // streaming: evict-first, don't churn L2
        float4 t = __ldcs(&tqr[i]);
        qs = fmaf(h.x, w.x, qs); qs = fmaf(h.y, w.y, qs);
        qs = fmaf(h.z, w.z, qs); qs = fmaf(h.w, w.w, qs);
        ns = fmaf(t.x, w.x, ns); ns = fmaf(t.y, w.y, ns);
        ns = fmaf(t.z, w.z, ns); ns = fmaf(t.w, w.w, ns);
    }
    // Remainder: 196 float4s handled by the first 196 threads.
    if (threadIdx.x < REMAIN) {
        const int i = FULL_ITERS * THREADS + threadIdx.x;
        float4 w = w4[i];
        float4 h = __ldcs(&hsr[i]);
        float4 t = __ldcs(&tqr[i]);
        qs = fmaf(h.x, w.x, qs); qs = fmaf(h.y, w.y, qs);
        qs = fmaf(h.z, w.z, qs); qs = fmaf(h.w, w.w, qs);
        ns = fmaf(t.x, w.x, ns); ns = fmaf(t.y, w.y, ns);
        ns = fmaf(t.z, w.z, ns); ns = fmaf(t.w, w.w, ns);
    }

    // Warp reduce both sums
    #pragma unroll
    for (int off = 16; off > 0; off >>= 1) {
        qs += __shfl_down_sync(0xFFFFFFFFu, qs, off);
        ns += __shfl_down_sync(0xFFFFFFFFu, ns, off);
    }

    __shared__ float sq[THREADS / 32];
    __shared__ float sn[THREADS / 32];
    __shared__ bool  s_is_last;
    const int lane = threadIdx.x & 31;
    const int wid  = threadIdx.x >> 5;
    if (lane == 0) { sq[wid] = qs; sn[wid] = ns; }
    __syncthreads();

    if (threadIdx.x == 0) {
        float q = 0.0f, n = 0.0f;
        #pragma unroll
        for (int w = 0; w < THREADS / 32; w++) { q += sq[w]; n += sn[w]; }
        const float b = bias[0];
        const float qv  = fmaxf(q + b, 0.0f);
        const float nqv = fmaxf(n + b, 0.0f);
        const float ps  = fabsf(rewards[row] + discount[0] * nqv - qv);
        g_row_loss[row] = is_done[row] ? 0.0f : ps;
        __threadfence();
        unsigned int prev = atomicAdd(&g_arrived, 1u);
        s_is_last = (prev == (unsigned int)(gridDim.x - 1));
    }
    __syncthreads();

    if (s_is_last) {
        __threadfence();
        __syncthreads();
        // Deterministic fixed-order reduction of all rows (vectorized).
        __shared__ float s[THREADS];
        const float4* rl4 = reinterpret_cast<const float4*>(g_row_loss);
        float sum = 0.0f;
        #pragma unroll
        for (int i = threadIdx.x; i < B_ROWS / 4; i += THREADS) {
            float4 v = rl4[i];
            sum += (v.x + v.y) + (v.z + v.w);
        }
        s[threadIdx.x] = sum;
        __syncthreads();
        #pragma unroll
        for (int st = THREADS / 2; st > 0; st >>= 1) {
            if (threadIdx.x < st) s[threadIdx.x] += s[threadIdx.x + st];
            __syncthreads();
        }
        if (threadIdx.x == 0) {
            out[0] = s[0] / (float)B_ROWS;
            g_arrived = 0;  // reset for next graph replay
        }
    }
}

extern "C" void kernel_launch(void* const* d_in, const int* in_sizes, int n_in,
                              void* d_out, int out_size) {
    const float*         hs       = (const float*)d_in[0];
    // d_in[1] = actions (unused by reference)
    const float*         rewards  = (const float*)d_in[2];
    const float*         discount = (const float*)d_in[3];
    const float*         tq       = (const float*)d_in[4];
    const unsigned char* is_done  = (const unsigned char*)d_in[5];
    const float*         W        = (const float*)d_in[6];
    const float*         bias     = (const float*)d_in[7];
    float* out = (float*)d_out;

    dq_fused_kernel<<<B_ROWS, THREADS>>>(hs, tq, rewards, discount, is_done, W, bias, out);
}